// round 3
// baseline (speedup 1.0000x reference)
#include <cuda_runtime.h>
#include <math.h>

#define BB 64
#define TT 512
#define EE 256
#define HH 200
#define G4 800          // 4*H
#define CC 20
#define M_ROWS (BB*TT)  // 32768
#define LN_EPS 1e-5f

// ---------------- scratch (device globals: allocation-free) ----------------
__device__ float g_x[M_ROWS * EE];        // LN'ed embeddings  [B*T, E]
__device__ float g_gxf[M_ROWS * G4];      // gates_x forward   [B*T, 4H]
__device__ float g_gxb[M_ROWS * G4];      // gates_x backward
__device__ float g_wtf[HH * G4];          // w_hh_f transposed [K=200][800]
__device__ float g_wtb[HH * G4];
__device__ float g_feats[M_ROWS * 2 * HH];// [B*T, 400]
__device__ float g_logits[M_ROWS * CC];   // [B*T, 20]
__device__ float g_lossb[BB];

__device__ __forceinline__ float sigf(float x) { return 1.f / (1.f + expf(-x)); }

// ---------------- 1. embedding + layernorm ----------------
__global__ void embed_ln_kernel(const int* __restrict__ words,
                                const float* __restrict__ table,
                                const float* __restrict__ gamma,
                                const float* __restrict__ beta) {
    int row = blockIdx.x;            // = b*T + t
    int tid = threadIdx.x;           // 256 threads = E
    int w = words[row];
    float v = table[(size_t)w * EE + tid];

    __shared__ float red[8];
    // mean
    float s = v;
    #pragma unroll
    for (int o = 16; o; o >>= 1) s += __shfl_xor_sync(~0u, s, o);
    if ((tid & 31) == 0) red[tid >> 5] = s;
    __syncthreads();
    float tot = 0.f;
    #pragma unroll
    for (int i = 0; i < 8; i++) tot += red[i];
    float mu = tot * (1.f / EE);
    __syncthreads();
    // var
    float d = v - mu;
    float s2 = d * d;
    #pragma unroll
    for (int o = 16; o; o >>= 1) s2 += __shfl_xor_sync(~0u, s2, o);
    if ((tid & 31) == 0) red[tid >> 5] = s2;
    __syncthreads();
    float tot2 = 0.f;
    #pragma unroll
    for (int i = 0; i < 8; i++) tot2 += red[i];
    float var = tot2 * (1.f / EE);

    g_x[(size_t)row * EE + tid] = d * rsqrtf(var + LN_EPS) * gamma[tid] + beta[tid];
}

// ---------------- 2. transpose w_hh -> [k][r] for coalesced recurrence ----------------
__global__ void transpose_w_kernel(const float* __restrict__ wf,
                                   const float* __restrict__ wb) {
    int idx = blockIdx.x * 256 + threadIdx.x;  // over 160000
    if (idx < HH * G4) {
        int r = idx / HH, k = idx % HH;
        g_wtf[k * G4 + r] = wf[idx];
        g_wtb[k * G4 + r] = wb[idx];
    }
}

// ---------------- 3. gates_x GEMM: G[m,n] = sum_k X[m,k]*W[n,k] + bias[n] ----------------
__global__ void gemm_gates_kernel(int dir,
                                  const float* __restrict__ W,
                                  const float* __restrict__ bias) {
    float* G = dir ? g_gxb : g_gxf;
    __shared__ float As[16][65];
    __shared__ float Bs[16][65];
    int tid = threadIdx.x;           // 256
    int tx = tid & 15, ty = tid >> 4;
    int m0 = blockIdx.y * 64, n0 = blockIdx.x * 64;
    float acc[4][4];
    #pragma unroll
    for (int i = 0; i < 4; i++)
        #pragma unroll
        for (int j = 0; j < 4; j++) acc[i][j] = 0.f;

    for (int k0 = 0; k0 < EE; k0 += 16) {
        #pragma unroll
        for (int q = 0; q < 4; q++) {
            int idx = tid + q * 256;
            int r = idx >> 4, kk = idx & 15;
            As[kk][r] = g_x[(size_t)(m0 + r) * EE + k0 + kk];
            int n = n0 + r;
            Bs[kk][r] = (n < G4) ? W[(size_t)n * EE + k0 + kk] : 0.f;
        }
        __syncthreads();
        #pragma unroll
        for (int kk = 0; kk < 16; kk++) {
            float a[4], b[4];
            #pragma unroll
            for (int i = 0; i < 4; i++) a[i] = As[kk][ty * 4 + i];
            #pragma unroll
            for (int j = 0; j < 4; j++) b[j] = Bs[kk][tx * 4 + j];
            #pragma unroll
            for (int i = 0; i < 4; i++)
                #pragma unroll
                for (int j = 0; j < 4; j++) acc[i][j] = fmaf(a[i], b[j], acc[i][j]);
        }
        __syncthreads();
    }
    #pragma unroll
    for (int i = 0; i < 4; i++) {
        int m = m0 + ty * 4 + i;
        #pragma unroll
        for (int j = 0; j < 4; j++) {
            int n = n0 + tx * 4 + j;
            if (n < G4) G[(size_t)m * G4 + n] = acc[i][j] + bias[n];
        }
    }
}

// ---------------- 4. BiLSTM recurrence (persistent, 2 batches per block) ----------------
__global__ void lstm_kernel(const int* __restrict__ seq_len) {
    int dir = blockIdx.x >> 5;       // 0..31 fwd, 32..63 bwd
    int bp  = blockIdx.x & 31;
    int b0 = bp, b1 = bp + 32;
    const float* gx = dir ? g_gxb : g_gxf;
    const float4* wt4 = (const float4*)(dir ? g_wtb : g_wtf);
    int len0 = seq_len[b0], len1 = seq_len[b1];

    __shared__ float h0[HH], c0[HH], h1[HH], c1[HH];
    __shared__ float gs0[G4], gs1[G4];
    int tid = threadIdx.x;           // 256
    for (int j = tid; j < HH; j += 256) { h0[j] = 0.f; c0[j] = 0.f; h1[j] = 0.f; c1[j] = 0.f; }
    __syncthreads();

    for (int s = 0; s < TT; s++) {
        int t = dir ? (TT - 1 - s) : s;
        if (tid < 200) {
            const float4* gx0 = (const float4*)(gx + ((size_t)b0 * TT + t) * G4);
            const float4* gx1 = (const float4*)(gx + ((size_t)b1 * TT + t) * G4);
            float4 a0 = gx0[tid];
            float4 a1 = gx1[tid];
            #pragma unroll 8
            for (int k = 0; k < HH; k++) {
                float4 w = wt4[k * 200 + tid];     // (k*800 + 4*tid)/4
                float hk0 = h0[k], hk1 = h1[k];
                a0.x = fmaf(w.x, hk0, a0.x); a0.y = fmaf(w.y, hk0, a0.y);
                a0.z = fmaf(w.z, hk0, a0.z); a0.w = fmaf(w.w, hk0, a0.w);
                a1.x = fmaf(w.x, hk1, a1.x); a1.y = fmaf(w.y, hk1, a1.y);
                a1.z = fmaf(w.z, hk1, a1.z); a1.w = fmaf(w.w, hk1, a1.w);
            }
            ((float4*)gs0)[tid] = a0;
            ((float4*)gs1)[tid] = a1;
        }
        __syncthreads();
        if (tid < HH) {
            int j = tid;
            // batch 0
            {
                float ig = sigf(gs0[j]);
                float fg = sigf(gs0[200 + j]);
                float gg = tanhf(gs0[400 + j]);
                float og = sigf(gs0[600 + j]);
                float cn = fmaf(fg, c0[j], ig * gg);
                float hn = og * tanhf(cn);
                if (t < len0) { c0[j] = cn; h0[j] = hn; }
                g_feats[((size_t)b0 * TT + t) * (2 * HH) + dir * HH + j] = h0[j];
            }
            // batch 1
            {
                float ig = sigf(gs1[j]);
                float fg = sigf(gs1[200 + j]);
                float gg = tanhf(gs1[400 + j]);
                float og = sigf(gs1[600 + j]);
                float cn = fmaf(fg, c1[j], ig * gg);
                float hn = og * tanhf(cn);
                if (t < len1) { c1[j] = cn; h1[j] = hn; }
                g_feats[((size_t)b1 * TT + t) * (2 * HH) + dir * HH + j] = h1[j];
            }
        }
        __syncthreads();
    }
}

// ---------------- 5. fc + log_softmax (warp per token) ----------------
__global__ void logits_kernel(const float* __restrict__ fcw,
                              const float* __restrict__ fcb) {
    int warp = (blockIdx.x * blockDim.x + threadIdx.x) >> 5;
    int lane = threadIdx.x & 31;
    if (warp >= M_ROWS) return;
    const float4* f4 = (const float4*)(g_feats + (size_t)warp * 400);
    float acc;
    if (lane < CC) {
        const float4* w4 = (const float4*)(fcw + (size_t)lane * 400);
        float a = 0.f;
        #pragma unroll 4
        for (int k = 0; k < 100; k++) {
            float4 f = f4[k], w = w4[k];
            a = fmaf(f.x, w.x, a); a = fmaf(f.y, w.y, a);
            a = fmaf(f.z, w.z, a); a = fmaf(f.w, w.w, a);
        }
        acc = a + fcb[lane];
    } else {
        acc = -INFINITY;
    }
    float m = acc;
    #pragma unroll
    for (int o = 16; o; o >>= 1) m = fmaxf(m, __shfl_xor_sync(~0u, m, o));
    float e = (lane < CC) ? expf(acc - m) : 0.f;
    float ss = e;
    #pragma unroll
    for (int o = 16; o; o >>= 1) ss += __shfl_xor_sync(~0u, ss, o);
    float lse = m + logf(ss);
    if (lane < CC) g_logits[(size_t)warp * CC + lane] = acc - lse;
}

// ---------------- 6. CRF NLL per batch (one warp per sample) ----------------
__global__ void crf_kernel(const int* __restrict__ target,
                           const int* __restrict__ seq_len,
                           const float* __restrict__ trans,
                           const float* __restrict__ start_s,
                           const float* __restrict__ end_s) {
    int b = blockIdx.x;
    int lane = threadIdx.x;          // 32
    __shared__ float s_trans[CC * CC];
    __shared__ float s_alpha[CC];
    for (int i = lane; i < CC * CC; i += 32) s_trans[i] = trans[i];
    int len = seq_len[b];
    const float* lg = g_logits + (size_t)b * TT * CC;
    const int* tg = target + (size_t)b * TT;
    if (lane < CC) s_alpha[lane] = start_s[lane] + lg[lane];
    __syncthreads();

    for (int t = 1; t < TT; t++) {
        if (t >= len) break;
        float newa = 0.f;
        if (lane < CC) {
            float m = -INFINITY;
            #pragma unroll
            for (int i = 0; i < CC; i++)
                m = fmaxf(m, s_alpha[i] + s_trans[i * CC + lane]);
            float s = 0.f;
            #pragma unroll
            for (int i = 0; i < CC; i++)
                s += expf(s_alpha[i] + s_trans[i * CC + lane] - m);
            newa = m + logf(s) + lg[t * CC + lane];
        }
        __syncthreads();
        if (lane < CC) s_alpha[lane] = newa;
        __syncthreads();
    }

    // logZ
    float v = (lane < CC) ? s_alpha[lane] + end_s[lane] : -INFINITY;
    float m = v;
    #pragma unroll
    for (int o = 16; o; o >>= 1) m = fmaxf(m, __shfl_xor_sync(~0u, m, o));
    float e = (lane < CC) ? expf(v - m) : 0.f;
    float ss = e;
    #pragma unroll
    for (int o = 16; o; o >>= 1) ss += __shfl_xor_sync(~0u, ss, o);
    float logZ = m + logf(ss);

    // gold score
    float es = 0.f;
    for (int t = lane; t < len; t += 32) es += lg[t * CC + tg[t]];
    float ts = 0.f;
    for (int t = 1 + lane; t < len; t += 32) ts += s_trans[tg[t - 1] * CC + tg[t]];
    float g = es + ts;
    #pragma unroll
    for (int o = 16; o; o >>= 1) g += __shfl_xor_sync(~0u, g, o);
    if (lane == 0) {
        float gold = g + start_s[tg[0]] + end_s[tg[len - 1]];
        g_lossb[b] = logZ - gold;
    }
}

// ---------------- 7. mean reduce ----------------
__global__ void reduce_loss_kernel(float* out) {
    int lane = threadIdx.x;          // 32
    float s = g_lossb[lane] + g_lossb[lane + 32];
    #pragma unroll
    for (int o = 16; o; o >>= 1) s += __shfl_xor_sync(~0u, s, o);
    if (lane == 0) out[0] = s * (1.f / BB);
}

// ---------------- launch ----------------
extern "C" void kernel_launch(void* const* d_in, const int* in_sizes, int n_in,
                              void* d_out, int out_size) {
    const int*   words   = (const int*)  d_in[0];
    const int*   seq_len = (const int*)  d_in[1];
    const int*   target  = (const int*)  d_in[2];
    const float* table   = (const float*)d_in[3];
    const float* gamma   = (const float*)d_in[4];
    const float* beta    = (const float*)d_in[5];
    const float* w_ih_f  = (const float*)d_in[6];
    const float* w_hh_f  = (const float*)d_in[7];
    const float* b_f     = (const float*)d_in[8];
    const float* w_ih_b  = (const float*)d_in[9];
    const float* w_hh_b  = (const float*)d_in[10];
    const float* b_b     = (const float*)d_in[11];
    const float* fc_w    = (const float*)d_in[12];
    const float* fc_b    = (const float*)d_in[13];
    const float* trans   = (const float*)d_in[14];
    const float* start_s = (const float*)d_in[15];
    const float* end_s   = (const float*)d_in[16];
    float* out = (float*)d_out;

    embed_ln_kernel<<<M_ROWS, 256>>>(words, table, gamma, beta);
    transpose_w_kernel<<<(HH * G4 + 255) / 256, 256>>>(w_hh_f, w_hh_b);

    dim3 ggrid((G4 + 63) / 64, M_ROWS / 64);
    gemm_gates_kernel<<<ggrid, 256>>>(0, w_ih_f, b_f);
    gemm_gates_kernel<<<ggrid, 256>>>(1, w_ih_b, b_b);

    lstm_kernel<<<64, 256>>>(seq_len);

    logits_kernel<<<M_ROWS / 8, 256>>>(fc_w, fc_b);

    crf_kernel<<<BB, 32>>>(target, seq_len, trans, start_s, end_s);
    reduce_loss_kernel<<<1, 32>>>(out);
}

// round 6
// speedup vs baseline: 3.3779x; 3.3779x over previous
#include <cuda_runtime.h>
#include <math.h>
#include <stdint.h>

#define BB 64
#define TT 512
#define EE 256
#define HH 200
#define G4 800          // 4*H
#define CC 20
#define M_ROWS (BB*TT)  // 32768
#define LN_EPS 1e-5f

// ---------------- scratch (device globals: allocation-free) ----------------
__device__ float g_x[M_ROWS * EE];        // LN'ed embeddings  [B*T, E]
__device__ float g_gxf[M_ROWS * G4];      // gates_x forward   [B*T, 4H]
__device__ float g_gxb[M_ROWS * G4];      // gates_x backward
__device__ float g_wtf[HH * G4];          // w_hh_f transposed [K=200][800]
__device__ float g_wtb[HH * G4];
__device__ float g_feats[M_ROWS * 2 * HH];// [B*T, 400]
__device__ float g_logits[M_ROWS * CC];   // [B*T, 20]
__device__ float g_lossb[BB];

__device__ __forceinline__ float sigf(float x) { return 1.f / (1.f + expf(-x)); }

__device__ __forceinline__ uint32_t smem_u32(const void* p) {
    uint32_t a;
    asm("{ .reg .u64 t; cvta.to.shared.u64 t, %1; cvt.u32.u64 %0, t; }" : "=r"(a) : "l"(p));
    return a;
}
__device__ __forceinline__ void st_dsmem_f32(uint32_t local_addr, uint32_t rank, float v) {
    uint32_t rem;
    asm volatile("mapa.shared::cluster.u32 %0, %1, %2;" : "=r"(rem) : "r"(local_addr), "r"(rank));
    asm volatile("st.shared::cluster.f32 [%0], %1;" :: "r"(rem), "f"(v) : "memory");
}
__device__ __forceinline__ void cluster_bar() {
    asm volatile("barrier.cluster.arrive.aligned;" ::: "memory");
    asm volatile("barrier.cluster.wait.aligned;" ::: "memory");
}

// ---------------- 1. embedding + layernorm ----------------
__global__ void embed_ln_kernel(const int* __restrict__ words,
                                const float* __restrict__ table,
                                const float* __restrict__ gamma,
                                const float* __restrict__ beta) {
    int row = blockIdx.x;
    int tid = threadIdx.x;           // 256 = E
    int w = words[row];
    float v = table[(size_t)w * EE + tid];

    __shared__ float red[8];
    float s = v;
    #pragma unroll
    for (int o = 16; o; o >>= 1) s += __shfl_xor_sync(~0u, s, o);
    if ((tid & 31) == 0) red[tid >> 5] = s;
    __syncthreads();
    float tot = 0.f;
    #pragma unroll
    for (int i = 0; i < 8; i++) tot += red[i];
    float mu = tot * (1.f / EE);
    __syncthreads();
    float d = v - mu;
    float s2 = d * d;
    #pragma unroll
    for (int o = 16; o; o >>= 1) s2 += __shfl_xor_sync(~0u, s2, o);
    if ((tid & 31) == 0) red[tid >> 5] = s2;
    __syncthreads();
    float tot2 = 0.f;
    #pragma unroll
    for (int i = 0; i < 8; i++) tot2 += red[i];
    float var = tot2 * (1.f / EE);

    g_x[(size_t)row * EE + tid] = d * rsqrtf(var + LN_EPS) * gamma[tid] + beta[tid];
}

// ---------------- 2. transpose w_hh -> [k][row] ----------------
__global__ void transpose_w_kernel(const float* __restrict__ wf,
                                   const float* __restrict__ wb) {
    int idx = blockIdx.x * 256 + threadIdx.x;
    if (idx < HH * G4) {
        int r = idx / HH, k = idx % HH;
        g_wtf[k * G4 + r] = wf[idx];
        g_wtb[k * G4 + r] = wb[idx];
    }
}

// ---------------- 3. gates_x GEMM (float4 fragments) ----------------
__global__ void gemm_gates_kernel(int dir,
                                  const float* __restrict__ W,
                                  const float* __restrict__ bias) {
    float* G = dir ? g_gxb : g_gxf;
    __shared__ __align__(16) float As[16][68];
    __shared__ __align__(16) float Bs[16][68];
    int tid = threadIdx.x;           // 256
    int tx = tid & 15, ty = tid >> 4;
    int m0 = blockIdx.y * 64, n0 = blockIdx.x * 64;
    float acc[4][4];
    #pragma unroll
    for (int i = 0; i < 4; i++)
        #pragma unroll
        for (int j = 0; j < 4; j++) acc[i][j] = 0.f;

    for (int k0 = 0; k0 < EE; k0 += 16) {
        #pragma unroll
        for (int q = 0; q < 4; q++) {
            int idx = tid + q * 256;
            int r = idx >> 4, kk = idx & 15;
            As[kk][r] = g_x[(size_t)(m0 + r) * EE + k0 + kk];
            int n = n0 + r;
            Bs[kk][r] = (n < G4) ? W[(size_t)n * EE + k0 + kk] : 0.f;
        }
        __syncthreads();
        #pragma unroll
        for (int kk = 0; kk < 16; kk++) {
            float4 a4 = *(const float4*)&As[kk][ty * 4];
            float4 b4 = *(const float4*)&Bs[kk][tx * 4];
            float a[4] = {a4.x, a4.y, a4.z, a4.w};
            float b[4] = {b4.x, b4.y, b4.z, b4.w};
            #pragma unroll
            for (int i = 0; i < 4; i++)
                #pragma unroll
                for (int j = 0; j < 4; j++) acc[i][j] = fmaf(a[i], b[j], acc[i][j]);
        }
        __syncthreads();
    }
    #pragma unroll
    for (int i = 0; i < 4; i++) {
        int m = m0 + ty * 4 + i;
        #pragma unroll
        for (int j = 0; j < 4; j++) {
            int n = n0 + tx * 4 + j;
            if (n < G4) G[(size_t)m * G4 + n] = acc[i][j] + bias[n];
        }
    }
}

// ---------------- 4. BiLSTM recurrence: 4-CTA clusters, SMEM-resident weights
// Cluster = 4 CTAs handling 4 batches of ONE direction.
// CTA rank r owns h-output slice [r*50, r*50+50): the 200 gate rows
// {g*200 + r*50 + j} as a 200x200 fp32 slice in SMEM (160 KB).
// h[200][4 batches] double-buffered, broadcast to peers via DSMEM each step.
#define NRANK 4
#define SLICE 50           // h outputs per rank
#define LROWS 200          // gate rows per rank
#define WS_ELEMS (HH * LROWS)        // 40000
#define H_ELEMS  (HH * NRANK)        // 800 per buffer
#define SMEM_FLOATS (WS_ELEMS + 2 * H_ELEMS + LROWS * NRANK)  // ws + h[2] + gbuf

__global__ void __cluster_dims__(NRANK, 1, 1) lstm_cluster_kernel(const int* __restrict__ seq_len) {
    extern __shared__ __align__(16) float smem[];
    float* ws   = smem;                        // [k=200][lr=200]
    float* hbuf = smem + WS_ELEMS;             // [2][200][4]
    float* gbuf = smem + WS_ELEMS + 2 * H_ELEMS; // [lr=200][4]

    int tid = threadIdx.x;                     // 256
    uint32_t cid  = blockIdx.x >> 2;           // 0..31
    uint32_t rank = blockIdx.x & 3;
    int dir  = cid >> 4;                       // 0 fwd, 1 bwd
    int bgrp = cid & 15;                       // 4 batches: bgrp*4..+3

    const float* gx = dir ? g_gxb : g_gxf;
    const float* wt = dir ? g_wtb : g_wtf;

    // stage weight slice: ws[k*200 + lr] = wt[k*800 + (lr/50)*200 + rank*50 + lr%50]
    for (int idx = tid; idx < WS_ELEMS; idx += 256) {
        int k = idx / LROWS, lr = idx - k * LROWS;
        int grow = (lr / SLICE) * HH + (int)rank * SLICE + (lr % SLICE);
        ws[idx] = wt[k * G4 + grow];
    }
    for (int i = tid; i < 2 * H_ELEMS + LROWS * NRANK; i += 256) hbuf[i] = 0.f;

    // per-thread persistent state (tid < 200): b = tid/50, j = tid%50
    int bl = tid / SLICE;                      // 0..3 (garbage for tid>=200, unused)
    int jl = tid - bl * SLICE;
    int bglob = bgrp * 4 + bl;
    int len = (tid < 200) ? seq_len[bglob] : 0;
    float c_reg = 0.f, h_reg = 0.f;

    // my gate row (for the gemv phase): lr = tid (tid<200)
    int grow = (tid / SLICE) * HH + (int)rank * SLICE + (tid % SLICE);

    __syncthreads();
    cluster_bar();                             // all CTAs initialized

    int p = 0;
    for (int s = 0; s < TT; s++) {
        int t = dir ? (TT - 1 - s) : s;

        if (tid < LROWS) {
            // acc[b] = gates_x[b][t][grow] + sum_k w[grow][k] * h[k][b]
            float a0 = gx[((size_t)(bgrp * 4 + 0) * TT + t) * G4 + grow];
            float a1 = gx[((size_t)(bgrp * 4 + 1) * TT + t) * G4 + grow];
            float a2 = gx[((size_t)(bgrp * 4 + 2) * TT + t) * G4 + grow];
            float a3 = gx[((size_t)(bgrp * 4 + 3) * TT + t) * G4 + grow];
            const float4* h4 = (const float4*)(hbuf + p * H_ELEMS);
            #pragma unroll 4
            for (int k = 0; k < HH; k++) {
                float w = ws[k * LROWS + tid];
                float4 h = h4[k];
                a0 = fmaf(w, h.x, a0);
                a1 = fmaf(w, h.y, a1);
                a2 = fmaf(w, h.z, a2);
                a3 = fmaf(w, h.w, a3);
            }
            ((float4*)gbuf)[tid] = make_float4(a0, a1, a2, a3);
        }
        __syncthreads();

        if (tid < LROWS) {
            float gi = gbuf[(0 * SLICE + jl) * NRANK + bl];
            float gf = gbuf[(1 * SLICE + jl) * NRANK + bl];
            float gg = gbuf[(2 * SLICE + jl) * NRANK + bl];
            float go = gbuf[(3 * SLICE + jl) * NRANK + bl];
            float cn = fmaf(sigf(gf), c_reg, sigf(gi) * tanhf(gg));
            float hn = sigf(go) * tanhf(cn);
            if (t < len) { c_reg = cn; h_reg = hn; }
            int jg = (int)rank * SLICE + jl;
            // broadcast h to all 4 ranks' next buffer
            uint32_t la = smem_u32(&hbuf[(1 - p) * H_ELEMS + jg * NRANK + bl]);
            #pragma unroll
            for (uint32_t r = 0; r < NRANK; r++) st_dsmem_f32(la, r, h_reg);
            g_feats[((size_t)bglob * TT + t) * (2 * HH) + dir * HH + jg] = h_reg;
        }
        cluster_bar();                         // h visible everywhere; also syncs CTA
        p ^= 1;
    }
}

// ---------------- 5. fc + log_softmax (warp per token) ----------------
__global__ void logits_kernel(const float* __restrict__ fcw,
                              const float* __restrict__ fcb) {
    int warp = (blockIdx.x * blockDim.x + threadIdx.x) >> 5;
    int lane = threadIdx.x & 31;
    if (warp >= M_ROWS) return;
    const float4* f4 = (const float4*)(g_feats + (size_t)warp * 400);
    float acc;
    if (lane < CC) {
        const float4* w4 = (const float4*)(fcw + (size_t)lane * 400);
        float a = 0.f;
        #pragma unroll 4
        for (int k = 0; k < 100; k++) {
            float4 f = f4[k], w = w4[k];
            a = fmaf(f.x, w.x, a); a = fmaf(f.y, w.y, a);
            a = fmaf(f.z, w.z, a); a = fmaf(f.w, w.w, a);
        }
        acc = a + fcb[lane];
    } else {
        acc = -INFINITY;
    }
    float m = acc;
    #pragma unroll
    for (int o = 16; o; o >>= 1) m = fmaxf(m, __shfl_xor_sync(~0u, m, o));
    float e = (lane < CC) ? expf(acc - m) : 0.f;
    float ss = e;
    #pragma unroll
    for (int o = 16; o; o >>= 1) ss += __shfl_xor_sync(~0u, ss, o);
    float lse = m + logf(ss);
    if (lane < CC) g_logits[(size_t)warp * CC + lane] = acc - lse;
}

// ---------------- 6. CRF NLL per batch (one warp per sample) ----------------
__global__ void crf_kernel(const int* __restrict__ target,
                           const int* __restrict__ seq_len,
                           const float* __restrict__ trans,
                           const float* __restrict__ start_s,
                           const float* __restrict__ end_s) {
    int b = blockIdx.x;
    int lane = threadIdx.x;          // 32
    __shared__ float s_trans[CC * CC];
    __shared__ float s_alpha[CC];
    for (int i = lane; i < CC * CC; i += 32) s_trans[i] = trans[i];
    int len = seq_len[b];
    const float* lg = g_logits + (size_t)b * TT * CC;
    const int* tg = target + (size_t)b * TT;
    if (lane < CC) s_alpha[lane] = start_s[lane] + lg[lane];
    __syncthreads();

    for (int t = 1; t < TT; t++) {
        if (t >= len) break;
        float newa = 0.f;
        if (lane < CC) {
            float m = -INFINITY;
            #pragma unroll
            for (int i = 0; i < CC; i++)
                m = fmaxf(m, s_alpha[i] + s_trans[i * CC + lane]);
            float s = 0.f;
            #pragma unroll
            for (int i = 0; i < CC; i++)
                s += expf(s_alpha[i] + s_trans[i * CC + lane] - m);
            newa = m + logf(s) + lg[t * CC + lane];
        }
        __syncthreads();
        if (lane < CC) s_alpha[lane] = newa;
        __syncthreads();
    }

    float v = (lane < CC) ? s_alpha[lane] + end_s[lane] : -INFINITY;
    float m = v;
    #pragma unroll
    for (int o = 16; o; o >>= 1) m = fmaxf(m, __shfl_xor_sync(~0u, m, o));
    float e = (lane < CC) ? expf(v - m) : 0.f;
    float ss = e;
    #pragma unroll
    for (int o = 16; o; o >>= 1) ss += __shfl_xor_sync(~0u, ss, o);
    float logZ = m + logf(ss);

    float es = 0.f;
    for (int t = lane; t < len; t += 32) es += lg[t * CC + tg[t]];
    float ts = 0.f;
    for (int t = 1 + lane; t < len; t += 32) ts += s_trans[tg[t - 1] * CC + tg[t]];
    float g = es + ts;
    #pragma unroll
    for (int o = 16; o; o >>= 1) g += __shfl_xor_sync(~0u, g, o);
    if (lane == 0) {
        float gold = g + start_s[tg[0]] + end_s[tg[len - 1]];
        g_lossb[b] = logZ - gold;
    }
}

// ---------------- 7. mean reduce ----------------
__global__ void reduce_loss_kernel(float* out) {
    int lane = threadIdx.x;          // 32
    float s = g_lossb[lane] + g_lossb[lane + 32];
    #pragma unroll
    for (int o = 16; o; o >>= 1) s += __shfl_xor_sync(~0u, s, o);
    if (lane == 0) out[0] = s * (1.f / BB);
}

// ---------------- launch ----------------
extern "C" void kernel_launch(void* const* d_in, const int* in_sizes, int n_in,
                              void* d_out, int out_size) {
    const int*   words   = (const int*)  d_in[0];
    const int*   seq_len = (const int*)  d_in[1];
    const int*   target  = (const int*)  d_in[2];
    const float* table   = (const float*)d_in[3];
    const float* gamma   = (const float*)d_in[4];
    const float* beta    = (const float*)d_in[5];
    const float* w_ih_f  = (const float*)d_in[6];
    const float* w_hh_f  = (const float*)d_in[7];
    const float* b_f     = (const float*)d_in[8];
    const float* w_ih_b  = (const float*)d_in[9];
    const float* w_hh_b  = (const float*)d_in[10];
    const float* b_b     = (const float*)d_in[11];
    const float* fc_w    = (const float*)d_in[12];
    const float* fc_b    = (const float*)d_in[13];
    const float* trans   = (const float*)d_in[14];
    const float* start_s = (const float*)d_in[15];
    const float* end_s   = (const float*)d_in[16];
    float* out = (float*)d_out;

    static const int lstm_smem = SMEM_FLOATS * (int)sizeof(float);  // ~169.6 KB
    cudaFuncSetAttribute(lstm_cluster_kernel,
                         cudaFuncAttributeMaxDynamicSharedMemorySize, lstm_smem);

    embed_ln_kernel<<<M_ROWS, 256>>>(words, table, gamma, beta);
    transpose_w_kernel<<<(HH * G4 + 255) / 256, 256>>>(w_hh_f, w_hh_b);

    dim3 ggrid((G4 + 63) / 64, M_ROWS / 64);
    gemm_gates_kernel<<<ggrid, 256>>>(0, w_ih_f, b_f);
    gemm_gates_kernel<<<ggrid, 256>>>(1, w_ih_b, b_b);

    lstm_cluster_kernel<<<32 * NRANK, 256, lstm_smem>>>(seq_len);

    logits_kernel<<<M_ROWS / 8, 256>>>(fc_w, fc_b);

    crf_kernel<<<BB, 32>>>(target, seq_len, trans, start_s, end_s);
    reduce_loss_kernel<<<1, 32>>>(out);
}

// round 9
// speedup vs baseline: 5.2834x; 1.5641x over previous
#include <cuda_runtime.h>
#include <math.h>
#include <stdint.h>

#define BB 64
#define TT 512
#define EE 256
#define HH 200
#define G4 800          // 4*H
#define CC 20
#define M_ROWS (BB*TT)  // 32768
#define LN_EPS 1e-5f

// ---------------- scratch (device globals: allocation-free) ----------------
__device__ float g_x[M_ROWS * EE];        // LN'ed embeddings  [B*T, E]
__device__ float g_gxf[M_ROWS * G4];      // gates_x forward   [B*T, 4H]
__device__ float g_gxb[M_ROWS * G4];      // gates_x backward
__device__ float g_wtf[HH * G4];          // w_hh_f transposed [K=200][800]
__device__ float g_wtb[HH * G4];
__device__ float g_feats[M_ROWS * 2 * HH];// [B*T, 400]
__device__ float g_logits[M_ROWS * CC];   // [B*T, 20]
__device__ float g_lossb[BB];

__device__ __forceinline__ float sigf(float x) { return 1.f / (1.f + expf(-x)); }

// ---- packed fp32x2 helpers (FFMA2: 2x fp32 FMA throughput on sm_103a) ----
__device__ __forceinline__ unsigned long long pack2(float x) {
    unsigned long long r;
    asm("mov.b64 %0, {%1, %1};" : "=l"(r) : "f"(x));
    return r;
}
__device__ __forceinline__ void fma2(unsigned long long& d,
                                     unsigned long long a, unsigned long long b) {
    asm("fma.rn.f32x2 %0, %1, %2, %0;" : "+l"(d) : "l"(a), "l"(b));
}
__device__ __forceinline__ float2 unpack2(unsigned long long v) {
    float2 f;
    asm("mov.b64 {%0, %1}, %2;" : "=f"(f.x), "=f"(f.y) : "l"(v));
    return f;
}

__device__ __forceinline__ uint32_t smem_u32(const void* p) {
    uint32_t a;
    asm("{ .reg .u64 t; cvta.to.shared.u64 t, %1; cvt.u32.u64 %0, t; }" : "=r"(a) : "l"(p));
    return a;
}
__device__ __forceinline__ void st_dsmem_f32(uint32_t local_addr, uint32_t rank, float v) {
    uint32_t rem;
    asm volatile("mapa.shared::cluster.u32 %0, %1, %2;" : "=r"(rem) : "r"(local_addr), "r"(rank));
    asm volatile("st.shared::cluster.f32 [%0], %1;" :: "r"(rem), "f"(v) : "memory");
}
__device__ __forceinline__ void cluster_bar() {
    asm volatile("barrier.cluster.arrive.aligned;" ::: "memory");
    asm volatile("barrier.cluster.wait.aligned;" ::: "memory");
}

// ---------------- 1. embedding + layernorm ----------------
__global__ void embed_ln_kernel(const int* __restrict__ words,
                                const float* __restrict__ table,
                                const float* __restrict__ gamma,
                                const float* __restrict__ beta) {
    int row = blockIdx.x;
    int tid = threadIdx.x;           // 256 = E
    int w = words[row];
    float v = table[(size_t)w * EE + tid];

    __shared__ float red[8];
    float s = v;
    #pragma unroll
    for (int o = 16; o; o >>= 1) s += __shfl_xor_sync(~0u, s, o);
    if ((tid & 31) == 0) red[tid >> 5] = s;
    __syncthreads();
    float tot = 0.f;
    #pragma unroll
    for (int i = 0; i < 8; i++) tot += red[i];
    float mu = tot * (1.f / EE);
    __syncthreads();
    float d = v - mu;
    float s2 = d * d;
    #pragma unroll
    for (int o = 16; o; o >>= 1) s2 += __shfl_xor_sync(~0u, s2, o);
    if ((tid & 31) == 0) red[tid >> 5] = s2;
    __syncthreads();
    float tot2 = 0.f;
    #pragma unroll
    for (int i = 0; i < 8; i++) tot2 += red[i];
    float var = tot2 * (1.f / EE);

    g_x[(size_t)row * EE + tid] = d * rsqrtf(var + LN_EPS) * gamma[tid] + beta[tid];
}

// ---------------- 2. transpose w_hh -> [k][row] ----------------
__global__ void transpose_w_kernel(const float* __restrict__ wf,
                                   const float* __restrict__ wb) {
    int idx = blockIdx.x * 256 + threadIdx.x;
    if (idx < HH * G4) {
        int r = idx / HH, k = idx % HH;
        g_wtf[k * G4 + r] = wf[idx];
        g_wtb[k * G4 + r] = wb[idx];
    }
}

// ---------------- 3. gates_x GEMM: 128x64 tile, 8x4/thread, f32x2 FMA ----------------
__global__ void __launch_bounds__(256) gemm_gates_kernel(int dir,
                                  const float* __restrict__ W,
                                  const float* __restrict__ bias) {
    float* G = dir ? g_gxb : g_gxf;
    __shared__ __align__(16) float As[16][132];   // [kk][row 0..127]
    __shared__ __align__(16) float Bs[16][68];    // [kk][n 0..63]
    int tid = threadIdx.x;           // 256
    int tx = tid & 15, ty = tid >> 4;
    int m0 = blockIdx.y * 128, n0 = blockIdx.x * 64;

    unsigned long long acc2[4][4];   // [row-pair p][col j] : rows m0+ty*8+2p,+2p+1
    #pragma unroll
    for (int p = 0; p < 4; p++)
        #pragma unroll
        for (int j = 0; j < 4; j++) acc2[p][j] = 0ull;

    for (int k0 = 0; k0 < EE; k0 += 16) {
        // A tile: 128 rows x 16 k = 512 float4, 2 per thread
        #pragma unroll
        for (int q = 0; q < 2; q++) {
            int f4 = tid * 2 + q;
            int row = f4 >> 2, kq = f4 & 3;
            float4 v = *(const float4*)&g_x[(size_t)(m0 + row) * EE + k0 + kq * 4];
            As[kq * 4 + 0][row] = v.x; As[kq * 4 + 1][row] = v.y;
            As[kq * 4 + 2][row] = v.z; As[kq * 4 + 3][row] = v.w;
        }
        // B tile: 64 n x 16 k = 256 float4, 1 per thread
        {
            int row = tid >> 2, kq = tid & 3;
            int n = n0 + row;
            float4 v = (n < G4) ? *(const float4*)&W[(size_t)n * EE + k0 + kq * 4]
                                : make_float4(0.f, 0.f, 0.f, 0.f);
            Bs[kq * 4 + 0][row] = v.x; Bs[kq * 4 + 1][row] = v.y;
            Bs[kq * 4 + 2][row] = v.z; Bs[kq * 4 + 3][row] = v.w;
        }
        __syncthreads();
        #pragma unroll
        for (int kk = 0; kk < 16; kk++) {
            ulonglong2 avA = *(const ulonglong2*)&As[kk][ty * 8];      // rows (0,1),(2,3)
            ulonglong2 avB = *(const ulonglong2*)&As[kk][ty * 8 + 4];  // rows (4,5),(6,7)
            float4 b4 = *(const float4*)&Bs[kk][tx * 4];
            unsigned long long ap[4] = {avA.x, avA.y, avB.x, avB.y};
            unsigned long long bd[4] = {pack2(b4.x), pack2(b4.y), pack2(b4.z), pack2(b4.w)};
            #pragma unroll
            for (int p = 0; p < 4; p++)
                #pragma unroll
                for (int j = 0; j < 4; j++) fma2(acc2[p][j], ap[p], bd[j]);
        }
        __syncthreads();
    }

    int nb = n0 + tx * 4;
    if (nb < G4) {
        float b0 = bias[nb], b1 = bias[nb + 1], b2 = bias[nb + 2], b3 = bias[nb + 3];
        #pragma unroll
        for (int p = 0; p < 4; p++) {
            float2 f0 = unpack2(acc2[p][0]);
            float2 f1 = unpack2(acc2[p][1]);
            float2 f2 = unpack2(acc2[p][2]);
            float2 f3 = unpack2(acc2[p][3]);
            int m = m0 + ty * 8 + p * 2;
            *(float4*)&G[(size_t)m * G4 + nb] =
                make_float4(f0.x + b0, f1.x + b1, f2.x + b2, f3.x + b3);
            *(float4*)&G[(size_t)(m + 1) * G4 + nb] =
                make_float4(f0.y + b0, f1.y + b1, f2.y + b2, f3.y + b3);
        }
    }
}

// ---------------- 4. BiLSTM recurrence: 4-CTA clusters, SMEM weights, f32x2 ----------------
#define NRANK 4
#define SLICE 50
#define LROWS 200
#define WS_ELEMS (HH * LROWS)        // 40000
#define H_ELEMS  (HH * NRANK)        // 800 per buffer
#define SMEM_FLOATS (WS_ELEMS + 2 * H_ELEMS + LROWS * NRANK)

__global__ void __cluster_dims__(NRANK, 1, 1) lstm_cluster_kernel(const int* __restrict__ seq_len) {
    extern __shared__ __align__(16) float smem[];
    float* ws   = smem;                          // [k=200][lr=200]
    float* hbuf = smem + WS_ELEMS;               // [2][200][4]
    float* gbuf = smem + WS_ELEMS + 2 * H_ELEMS; // [lr=200][4]

    int tid = threadIdx.x;                       // 256
    uint32_t cid  = blockIdx.x >> 2;
    uint32_t rank = blockIdx.x & 3;
    int dir  = cid >> 4;
    int bgrp = cid & 15;

    const float* gx = dir ? g_gxb : g_gxf;
    const float* wt = dir ? g_wtb : g_wtf;

    for (int idx = tid; idx < WS_ELEMS; idx += 256) {
        int k = idx / LROWS, lr = idx - k * LROWS;
        int gr = (lr / SLICE) * HH + (int)rank * SLICE + (lr % SLICE);
        ws[idx] = wt[k * G4 + gr];
    }
    for (int i = tid; i < 2 * H_ELEMS + LROWS * NRANK; i += 256) hbuf[i] = 0.f;

    int l0 = seq_len[bgrp * 4 + 0], l1 = seq_len[bgrp * 4 + 1];
    int l2 = seq_len[bgrp * 4 + 2], l3 = seq_len[bgrp * 4 + 3];
    int maxlen = max(max(l0, l1), max(l2, l3));

    int bl = tid / SLICE;
    int jl = tid - bl * SLICE;
    int bglob = bgrp * 4 + bl;
    int len = (tid < LROWS) ? seq_len[bglob] : 0;
    float c_reg = 0.f, h_reg = 0.f;
    int grow = (tid / SLICE) * HH + (int)rank * SLICE + (tid % SLICE);
    int jg = (int)rank * SLICE + jl;

    __syncthreads();
    cluster_bar();

    int p = 0;
    for (int s = 0; s < maxlen; s++) {
        int t = dir ? (maxlen - 1 - s) : s;

        if (tid < LROWS) {
            // issue gx loads first (overlap with gemv), consume after the loop
            float g0 = gx[((size_t)(bgrp * 4 + 0) * TT + t) * G4 + grow];
            float g1 = gx[((size_t)(bgrp * 4 + 1) * TT + t) * G4 + grow];
            float g2 = gx[((size_t)(bgrp * 4 + 2) * TT + t) * G4 + grow];
            float g3 = gx[((size_t)(bgrp * 4 + 3) * TT + t) * G4 + grow];
            unsigned long long a01 = 0ull, a23 = 0ull;
            const ulonglong2* h2 = (const ulonglong2*)(hbuf + p * H_ELEMS);
            #pragma unroll 8
            for (int k = 0; k < HH; k++) {
                unsigned long long w2 = pack2(ws[k * LROWS + tid]);
                ulonglong2 hv = h2[k];
                fma2(a01, w2, hv.x);
                fma2(a23, w2, hv.y);
            }
            float2 f01 = unpack2(a01);
            float2 f23 = unpack2(a23);
            ((float4*)gbuf)[tid] = make_float4(f01.x + g0, f01.y + g1,
                                               f23.x + g2, f23.y + g3);
        }
        __syncthreads();

        if (tid < LROWS) {
            float gi = gbuf[(0 * SLICE + jl) * NRANK + bl];
            float gf = gbuf[(1 * SLICE + jl) * NRANK + bl];
            float gg = gbuf[(2 * SLICE + jl) * NRANK + bl];
            float go = gbuf[(3 * SLICE + jl) * NRANK + bl];
            float cn = fmaf(sigf(gf), c_reg, sigf(gi) * tanhf(gg));
            float hn = sigf(go) * tanhf(cn);
            if (t < len) { c_reg = cn; h_reg = hn; }
            uint32_t la = smem_u32(&hbuf[(1 - p) * H_ELEMS + jg * NRANK + bl]);
            #pragma unroll
            for (uint32_t r = 0; r < NRANK; r++) st_dsmem_f32(la, r, h_reg);
            g_feats[((size_t)bglob * TT + t) * (2 * HH) + dir * HH + jg] = h_reg;
        }
        cluster_bar();
        p ^= 1;
    }

    // tail t in [maxlen, TT): fwd -> frozen h, bwd -> zeros. No gemv/barriers.
    if (tid < LROWS) {
        float tv = dir ? 0.f : h_reg;
        for (int t = maxlen; t < TT; t++)
            g_feats[((size_t)bglob * TT + t) * (2 * HH) + dir * HH + jg] = tv;
    }
}

// ---------------- 5. fc + log_softmax (warp per token) ----------------
__global__ void logits_kernel(const float* __restrict__ fcw,
                              const float* __restrict__ fcb) {
    int warp = (blockIdx.x * blockDim.x + threadIdx.x) >> 5;
    int lane = threadIdx.x & 31;
    if (warp >= M_ROWS) return;
    const float4* f4 = (const float4*)(g_feats + (size_t)warp * 400);
    float acc;
    if (lane < CC) {
        const float4* w4 = (const float4*)(fcw + (size_t)lane * 400);
        float a = 0.f;
        #pragma unroll 4
        for (int k = 0; k < 100; k++) {
            float4 f = f4[k], w = w4[k];
            a = fmaf(f.x, w.x, a); a = fmaf(f.y, w.y, a);
            a = fmaf(f.z, w.z, a); a = fmaf(f.w, w.w, a);
        }
        acc = a + fcb[lane];
    } else {
        acc = -INFINITY;
    }
    float m = acc;
    #pragma unroll
    for (int o = 16; o; o >>= 1) m = fmaxf(m, __shfl_xor_sync(~0u, m, o));
    float e = (lane < CC) ? expf(acc - m) : 0.f;
    float ss = e;
    #pragma unroll
    for (int o = 16; o; o >>= 1) ss += __shfl_xor_sync(~0u, ss, o);
    float lse = m + logf(ss);
    if (lane < CC) g_logits[(size_t)warp * CC + lane] = acc - lse;
}

// ---------------- 6. CRF NLL per batch (one warp per sample) ----------------
__global__ void crf_kernel(const int* __restrict__ target,
                           const int* __restrict__ seq_len,
                           const float* __restrict__ trans,
                           const float* __restrict__ start_s,
                           const float* __restrict__ end_s) {
    int b = blockIdx.x;
    int lane = threadIdx.x;          // 32
    __shared__ float s_trans[CC * CC];
    __shared__ float s_alpha[CC];
    for (int i = lane; i < CC * CC; i += 32) s_trans[i] = trans[i];
    int len = seq_len[b];
    const float* lg = g_logits + (size_t)b * TT * CC;
    const int* tg = target + (size_t)b * TT;
    if (lane < CC) s_alpha[lane] = start_s[lane] + lg[lane];
    __syncthreads();

    for (int t = 1; t < TT; t++) {
        if (t >= len) break;
        float newa = 0.f;
        if (lane < CC) {
            float m = -INFINITY;
            #pragma unroll
            for (int i = 0; i < CC; i++)
                m = fmaxf(m, s_alpha[i] + s_trans[i * CC + lane]);
            float s = 0.f;
            #pragma unroll
            for (int i = 0; i < CC; i++)
                s += expf(s_alpha[i] + s_trans[i * CC + lane] - m);
            newa = m + logf(s) + lg[t * CC + lane];
        }
        __syncthreads();
        if (lane < CC) s_alpha[lane] = newa;
        __syncthreads();
    }

    float v = (lane < CC) ? s_alpha[lane] + end_s[lane] : -INFINITY;
    float m = v;
    #pragma unroll
    for (int o = 16; o; o >>= 1) m = fmaxf(m, __shfl_xor_sync(~0u, m, o));
    float e = (lane < CC) ? expf(v - m) : 0.f;
    float ss = e;
    #pragma unroll
    for (int o = 16; o; o >>= 1) ss += __shfl_xor_sync(~0u, ss, o);
    float logZ = m + logf(ss);

    float es = 0.f;
    for (int t = lane; t < len; t += 32) es += lg[t * CC + tg[t]];
    float ts = 0.f;
    for (int t = 1 + lane; t < len; t += 32) ts += s_trans[tg[t - 1] * CC + tg[t]];
    float g = es + ts;
    #pragma unroll
    for (int o = 16; o; o >>= 1) g += __shfl_xor_sync(~0u, g, o);
    if (lane == 0) {
        float gold = g + start_s[tg[0]] + end_s[tg[len - 1]];
        g_lossb[b] = logZ - gold;
    }
}

// ---------------- 7. mean reduce ----------------
__global__ void reduce_loss_kernel(float* out) {
    int lane = threadIdx.x;          // 32
    float s = g_lossb[lane] + g_lossb[lane + 32];
    #pragma unroll
    for (int o = 16; o; o >>= 1) s += __shfl_xor_sync(~0u, s, o);
    if (lane == 0) out[0] = s * (1.f / BB);
}

// ---------------- launch ----------------
extern "C" void kernel_launch(void* const* d_in, const int* in_sizes, int n_in,
                              void* d_out, int out_size) {
    const int*   words   = (const int*)  d_in[0];
    const int*   seq_len = (const int*)  d_in[1];
    const int*   target  = (const int*)  d_in[2];
    const float* table   = (const float*)d_in[3];
    const float* gamma   = (const float*)d_in[4];
    const float* beta    = (const float*)d_in[5];
    const float* w_ih_f  = (const float*)d_in[6];
    const float* w_hh_f  = (const float*)d_in[7];
    const float* b_f     = (const float*)d_in[8];
    const float* w_ih_b  = (const float*)d_in[9];
    const float* w_hh_b  = (const float*)d_in[10];
    const float* b_b     = (const float*)d_in[11];
    const float* fc_w    = (const float*)d_in[12];
    const float* fc_b    = (const float*)d_in[13];
    const float* trans   = (const float*)d_in[14];
    const float* start_s = (const float*)d_in[15];
    const float* end_s   = (const float*)d_in[16];
    float* out = (float*)d_out;

    static const int lstm_smem = SMEM_FLOATS * (int)sizeof(float);  // ~169.6 KB
    cudaFuncSetAttribute(lstm_cluster_kernel,
                         cudaFuncAttributeMaxDynamicSharedMemorySize, lstm_smem);

    embed_ln_kernel<<<M_ROWS, 256>>>(words, table, gamma, beta);
    transpose_w_kernel<<<(HH * G4 + 255) / 256, 256>>>(w_hh_f, w_hh_b);

    dim3 ggrid((G4 + 63) / 64, M_ROWS / 128);
    gemm_gates_kernel<<<ggrid, 256>>>(0, w_ih_f, b_f);
    gemm_gates_kernel<<<ggrid, 256>>>(1, w_ih_b, b_b);

    lstm_cluster_kernel<<<32 * NRANK, 256, lstm_smem>>>(seq_len);

    logits_kernel<<<M_ROWS / 8, 256>>>(fc_w, fc_b);

    crf_kernel<<<BB, 32>>>(target, seq_len, trans, start_s, end_s);
    reduce_loss_kernel<<<1, 32>>>(out);
}

// round 10
// speedup vs baseline: 5.3583x; 1.0142x over previous
#include <cuda_runtime.h>
#include <math.h>
#include <stdint.h>

#define BB 64
#define TT 512
#define EE 256
#define HH 200
#define G4 800          // 4*H
#define CC 20
#define M_ROWS (BB*TT)  // 32768
#define LN_EPS 1e-5f

typedef unsigned long long ull;

// ---------------- scratch (device globals: allocation-free) ----------------
__device__ float g_x[M_ROWS * EE];        // LN'ed embeddings  [B*T, E]
__device__ float g_gxf[M_ROWS * G4];      // gates_x forward   [B*T, 4H]
__device__ float g_gxb[M_ROWS * G4];      // gates_x backward
__device__ float g_wtf[HH * G4];          // w_hh_f transposed [K=200][800]
__device__ float g_wtb[HH * G4];
__device__ float g_feats[M_ROWS * 2 * HH];// [B*T, 400]
__device__ float g_logits[M_ROWS * CC];   // [B*T, 20]
__device__ float g_lossb[BB];

__device__ __forceinline__ float sigf(float x) { return 1.f / (1.f + expf(-x)); }

// ---- packed fp32x2 helpers (FFMA2: 2x fp32 FMA throughput on sm_103a) ----
__device__ __forceinline__ ull pack2(float x) {
    ull r;
    asm("mov.b64 %0, {%1, %1};" : "=l"(r) : "f"(x));
    return r;
}
__device__ __forceinline__ ull pack2f(float lo, float hi) {
    ull r;
    asm("mov.b64 %0, {%1, %2};" : "=l"(r) : "f"(lo), "f"(hi));
    return r;
}
__device__ __forceinline__ void fma2(ull& d, ull a, ull b) {
    asm("fma.rn.f32x2 %0, %1, %2, %0;" : "+l"(d) : "l"(a), "l"(b));
}
__device__ __forceinline__ void add2(ull& d, ull a) {
    asm("add.rn.f32x2 %0, %0, %1;" : "+l"(d) : "l"(a));
}
__device__ __forceinline__ float2 unpack2(ull v) {
    float2 f;
    asm("mov.b64 {%0, %1}, %2;" : "=f"(f.x), "=f"(f.y) : "l"(v));
    return f;
}

__device__ __forceinline__ uint32_t smem_u32(const void* p) {
    uint32_t a;
    asm("{ .reg .u64 t; cvta.to.shared.u64 t, %1; cvt.u32.u64 %0, t; }" : "=r"(a) : "l"(p));
    return a;
}
__device__ __forceinline__ uint32_t mapa_rank(uint32_t local_addr, uint32_t rank) {
    uint32_t rem;
    asm("mapa.shared::cluster.u32 %0, %1, %2;" : "=r"(rem) : "r"(local_addr), "r"(rank));
    return rem;
}
__device__ __forceinline__ void st_cluster_f32(uint32_t addr, float v) {
    asm volatile("st.shared::cluster.f32 [%0], %1;" :: "r"(addr), "f"(v) : "memory");
}
__device__ __forceinline__ void cluster_bar() {
    asm volatile("barrier.cluster.arrive.aligned;" ::: "memory");
    asm volatile("barrier.cluster.wait.aligned;" ::: "memory");
}

// ---------------- 1. embedding + layernorm ----------------
__global__ void embed_ln_kernel(const int* __restrict__ words,
                                const float* __restrict__ table,
                                const float* __restrict__ gamma,
                                const float* __restrict__ beta) {
    int row = blockIdx.x;
    int tid = threadIdx.x;           // 256 = E
    int w = words[row];
    float v = table[(size_t)w * EE + tid];

    __shared__ float red[8];
    float s = v;
    #pragma unroll
    for (int o = 16; o; o >>= 1) s += __shfl_xor_sync(~0u, s, o);
    if ((tid & 31) == 0) red[tid >> 5] = s;
    __syncthreads();
    float tot = 0.f;
    #pragma unroll
    for (int i = 0; i < 8; i++) tot += red[i];
    float mu = tot * (1.f / EE);
    __syncthreads();
    float d = v - mu;
    float s2 = d * d;
    #pragma unroll
    for (int o = 16; o; o >>= 1) s2 += __shfl_xor_sync(~0u, s2, o);
    if ((tid & 31) == 0) red[tid >> 5] = s2;
    __syncthreads();
    float tot2 = 0.f;
    #pragma unroll
    for (int i = 0; i < 8; i++) tot2 += red[i];
    float var = tot2 * (1.f / EE);

    g_x[(size_t)row * EE + tid] = d * rsqrtf(var + LN_EPS) * gamma[tid] + beta[tid];
}

// ---------------- 2. transpose w_hh -> [k][row] ----------------
__global__ void transpose_w_kernel(const float* __restrict__ wf,
                                   const float* __restrict__ wb) {
    int idx = blockIdx.x * 256 + threadIdx.x;
    if (idx < HH * G4) {
        int r = idx / HH, k = idx % HH;
        g_wtf[k * G4 + r] = wf[idx];
        g_wtb[k * G4 + r] = wb[idx];
    }
}

// ---------------- 3. gates_x GEMM: both dirs fused, 128x64 tile, f32x2 ----------------
__global__ void __launch_bounds__(256) gemm_gates_kernel(
                                  const float* __restrict__ Wf,
                                  const float* __restrict__ biasf,
                                  const float* __restrict__ Wb,
                                  const float* __restrict__ biasb) {
    int dir = blockIdx.z;
    float* G = dir ? g_gxb : g_gxf;
    const float* W = dir ? Wb : Wf;
    const float* bias = dir ? biasb : biasf;
    __shared__ __align__(16) float As[16][132];   // [kk][row 0..127]
    __shared__ __align__(16) float Bs[16][68];    // [kk][n 0..63]
    int tid = threadIdx.x;           // 256
    int tx = tid & 15, ty = tid >> 4;
    int m0 = blockIdx.y * 128, n0 = blockIdx.x * 64;

    ull acc2[4][4];
    #pragma unroll
    for (int p = 0; p < 4; p++)
        #pragma unroll
        for (int j = 0; j < 4; j++) acc2[p][j] = 0ull;

    for (int k0 = 0; k0 < EE; k0 += 16) {
        #pragma unroll
        for (int q = 0; q < 2; q++) {
            int f4 = tid * 2 + q;
            int row = f4 >> 2, kq = f4 & 3;
            float4 v = *(const float4*)&g_x[(size_t)(m0 + row) * EE + k0 + kq * 4];
            As[kq * 4 + 0][row] = v.x; As[kq * 4 + 1][row] = v.y;
            As[kq * 4 + 2][row] = v.z; As[kq * 4 + 3][row] = v.w;
        }
        {
            int row = tid >> 2, kq = tid & 3;
            int n = n0 + row;
            float4 v = (n < G4) ? *(const float4*)&W[(size_t)n * EE + k0 + kq * 4]
                                : make_float4(0.f, 0.f, 0.f, 0.f);
            Bs[kq * 4 + 0][row] = v.x; Bs[kq * 4 + 1][row] = v.y;
            Bs[kq * 4 + 2][row] = v.z; Bs[kq * 4 + 3][row] = v.w;
        }
        __syncthreads();
        #pragma unroll
        for (int kk = 0; kk < 16; kk++) {
            ulonglong2 avA = *(const ulonglong2*)&As[kk][ty * 8];
            ulonglong2 avB = *(const ulonglong2*)&As[kk][ty * 8 + 4];
            float4 b4 = *(const float4*)&Bs[kk][tx * 4];
            ull ap[4] = {avA.x, avA.y, avB.x, avB.y};
            ull bd[4] = {pack2(b4.x), pack2(b4.y), pack2(b4.z), pack2(b4.w)};
            #pragma unroll
            for (int p = 0; p < 4; p++)
                #pragma unroll
                for (int j = 0; j < 4; j++) fma2(acc2[p][j], ap[p], bd[j]);
        }
        __syncthreads();
    }

    int nb = n0 + tx * 4;
    if (nb < G4) {
        float b0 = bias[nb], b1 = bias[nb + 1], b2 = bias[nb + 2], b3 = bias[nb + 3];
        #pragma unroll
        for (int p = 0; p < 4; p++) {
            float2 f0 = unpack2(acc2[p][0]);
            float2 f1 = unpack2(acc2[p][1]);
            float2 f2 = unpack2(acc2[p][2]);
            float2 f3 = unpack2(acc2[p][3]);
            int m = m0 + ty * 8 + p * 2;
            *(float4*)&G[(size_t)m * G4 + nb] =
                make_float4(f0.x + b0, f1.x + b1, f2.x + b2, f3.x + b3);
            *(float4*)&G[(size_t)(m + 1) * G4 + nb] =
                make_float4(f0.y + b0, f1.y + b1, f2.y + b2, f3.y + b3);
        }
    }
}

// ---------------- 4. BiLSTM recurrence: 4-CTA clusters, 8 batches, k-split ----------------
#define NRANK 4
#define NB 8                          // batches per cluster
#define SLICE 50
#define LROWS 200
#define WS_ELEMS (HH * LROWS)         // 40000
#define HB_ELEMS (HH * NB)            // 1600 per parity
#define GP_ELEMS (LROWS * NB)         // 1600
#define LSTM_SMEM_FLOATS (WS_ELEMS + 2 * HB_ELEMS + 2 * GP_ELEMS)  // 46400 -> 185.6 KB

__global__ void __cluster_dims__(NRANK, 1, 1) __launch_bounds__(512, 1)
lstm_cluster_kernel(const int* __restrict__ seq_len) {
    extern __shared__ __align__(16) float smem[];
    float* ws    = smem;                        // [k=200][lr=200]
    float* hbuf  = smem + WS_ELEMS;             // [2][k=200][b=8]
    float* gpart = hbuf + 2 * HB_ELEMS;         // [lr=200][b=8] partial (k-half 1)
    float* gbuf  = gpart + GP_ELEMS;            // [lr=200][b=8] final

    int tid = threadIdx.x;                      // 512
    uint32_t cid  = blockIdx.x >> 2;            // 0..15
    uint32_t rank = blockIdx.x & 3;
    int dir  = (int)(cid >> 3);                 // 0 fwd, 1 bwd
    int bgrp = (int)(cid & 7);                  // batches bgrp*8 .. +7

    const float* gx = dir ? g_gxb : g_gxf;
    const float* wt = dir ? g_wtb : g_wtf;

    // stage weight slice
    for (int idx = tid; idx < WS_ELEMS; idx += 512) {
        int k = idx / LROWS, lr = idx - k * LROWS;
        int gr = (lr / SLICE) * HH + (int)rank * SLICE + (lr % SLICE);
        ws[idx] = wt[k * G4 + gr];
    }
    for (int i = tid; i < 2 * HB_ELEMS + 2 * GP_ELEMS; i += 512) hbuf[i] = 0.f;

    int maxlen = 0;
    #pragma unroll
    for (int b = 0; b < NB; b++) maxlen = max(maxlen, seq_len[bgrp * NB + b]);

    // gemv role: (half, r) — thread computes row r over k-half
    int r    = tid & 255;
    int half = tid >> 8;
    int grow = (r / SLICE) * HH + (int)rank * SLICE + (r % SLICE);
    const float* gxbase[NB];
    if (half == 0 && r < LROWS) {
        #pragma unroll
        for (int b = 0; b < NB; b++)
            gxbase[b] = gx + (size_t)(bgrp * NB + b) * TT * G4 + grow;
    }

    // epilogue role: tid = jl*8 + bl  (tid < 400)
    int bl = tid & 7;
    int jl = tid >> 3;
    int bglob = bgrp * NB + bl;
    int len = (tid < 400) ? seq_len[bglob] : 0;
    int jg = (int)rank * SLICE + jl;
    float c_reg = 0.f, h_reg = 0.f;

    // hoisted remote smem base addresses (one mapa per rank, once)
    uint32_t hb_local = smem_u32(hbuf);
    uint32_t rem0 = mapa_rank(hb_local, 0);
    uint32_t rem1 = mapa_rank(hb_local, 1);
    uint32_t rem2 = mapa_rank(hb_local, 2);
    uint32_t rem3 = mapa_rank(hb_local, 3);
    uint32_t my_off = ((uint32_t)rank * 400 + (uint32_t)tid) * 4;  // hbuf[jg*8+bl]

    __syncthreads();
    cluster_bar();

    int p = 0;
    for (int s = 0; s < maxlen; s++) {
        int t = dir ? (maxlen - 1 - s) : s;

        ull a0 = 0ull, a1 = 0ull, a2 = 0ull, a3 = 0ull;
        float gxv[NB];
        if (r < LROWS) {
            if (half == 0) {
                #pragma unroll
                for (int b = 0; b < NB; b++) gxv[b] = gxbase[b][(size_t)t * G4];
            }
            const ulonglong2* h4 = (const ulonglong2*)(hbuf + p * HB_ELEMS);
            int k0 = half * 100;
            #pragma unroll 4
            for (int k = k0; k < k0 + 100; k++) {
                ull w2 = pack2(ws[k * LROWS + r]);
                ulonglong2 hA = h4[2 * k];
                ulonglong2 hB = h4[2 * k + 1];
                fma2(a0, w2, hA.x);
                fma2(a1, w2, hA.y);
                fma2(a2, w2, hB.x);
                fma2(a3, w2, hB.y);
            }
            if (half) {
                ((ulonglong2*)gpart)[r * 2]     = make_ulonglong2(a0, a1);
                ((ulonglong2*)gpart)[r * 2 + 1] = make_ulonglong2(a2, a3);
            }
        }
        __syncthreads();

        if (half == 0 && r < LROWS) {
            ulonglong2 pA = ((ulonglong2*)gpart)[r * 2];
            ulonglong2 pB = ((ulonglong2*)gpart)[r * 2 + 1];
            add2(a0, pA.x); add2(a1, pA.y); add2(a2, pB.x); add2(a3, pB.y);
            add2(a0, pack2f(gxv[0], gxv[1]));
            add2(a1, pack2f(gxv[2], gxv[3]));
            add2(a2, pack2f(gxv[4], gxv[5]));
            add2(a3, pack2f(gxv[6], gxv[7]));
            ((ulonglong2*)gbuf)[r * 2]     = make_ulonglong2(a0, a1);
            ((ulonglong2*)gbuf)[r * 2 + 1] = make_ulonglong2(a2, a3);
        }
        __syncthreads();

        if (tid < 400) {
            float gi = gbuf[0 * 400 + tid];
            float gf = gbuf[1 * 400 + tid];
            float gg = gbuf[2 * 400 + tid];
            float go = gbuf[3 * 400 + tid];
            float cn = fmaf(sigf(gf), c_reg, sigf(gi) * tanhf(gg));
            float hn = sigf(go) * tanhf(cn);
            if (t < len) { c_reg = cn; h_reg = hn; }
            uint32_t off = (uint32_t)(1 - p) * (HB_ELEMS * 4) + my_off;
            st_cluster_f32(rem0 + off, h_reg);
            st_cluster_f32(rem1 + off, h_reg);
            st_cluster_f32(rem2 + off, h_reg);
            st_cluster_f32(rem3 + off, h_reg);
            g_feats[((size_t)bglob * TT + t) * (2 * HH) + dir * HH + jg] = h_reg;
        }
        cluster_bar();
        p ^= 1;
    }

    // tail t in [maxlen, TT): fwd -> frozen h, bwd -> zeros
    if (tid < 400) {
        float tv = dir ? 0.f : h_reg;
        for (int t = maxlen; t < TT; t++)
            g_feats[((size_t)bglob * TT + t) * (2 * HH) + dir * HH + jg] = tv;
    }
}

// ---------------- 5. fc + log_softmax (warp per token) ----------------
__global__ void logits_kernel(const float* __restrict__ fcw,
                              const float* __restrict__ fcb) {
    int warp = (blockIdx.x * blockDim.x + threadIdx.x) >> 5;
    int lane = threadIdx.x & 31;
    if (warp >= M_ROWS) return;
    const float4* f4 = (const float4*)(g_feats + (size_t)warp * 400);
    float acc;
    if (lane < CC) {
        const float4* w4 = (const float4*)(fcw + (size_t)lane * 400);
        float a = 0.f;
        #pragma unroll 4
        for (int k = 0; k < 100; k++) {
            float4 f = f4[k], w = w4[k];
            a = fmaf(f.x, w.x, a); a = fmaf(f.y, w.y, a);
            a = fmaf(f.z, w.z, a); a = fmaf(f.w, w.w, a);
        }
        acc = a + fcb[lane];
    } else {
        acc = -INFINITY;
    }
    float m = acc;
    #pragma unroll
    for (int o = 16; o; o >>= 1) m = fmaxf(m, __shfl_xor_sync(~0u, m, o));
    float e = (lane < CC) ? expf(acc - m) : 0.f;
    float ss = e;
    #pragma unroll
    for (int o = 16; o; o >>= 1) ss += __shfl_xor_sync(~0u, ss, o);
    float lse = m + logf(ss);
    if (lane < CC) g_logits[(size_t)warp * CC + lane] = acc - lse;
}

// ---------------- 6. CRF NLL per batch (one warp per sample) ----------------
__global__ void crf_kernel(const int* __restrict__ target,
                           const int* __restrict__ seq_len,
                           const float* __restrict__ trans,
                           const float* __restrict__ start_s,
                           const float* __restrict__ end_s) {
    int b = blockIdx.x;
    int lane = threadIdx.x;          // 32
    __shared__ float s_trans[CC * CC];
    __shared__ float s_alpha[CC];
    for (int i = lane; i < CC * CC; i += 32) s_trans[i] = trans[i];
    int len = seq_len[b];
    const float* lg = g_logits + (size_t)b * TT * CC;
    const int* tg = target + (size_t)b * TT;
    if (lane < CC) s_alpha[lane] = start_s[lane] + lg[lane];
    __syncthreads();

    for (int t = 1; t < TT; t++) {
        if (t >= len) break;
        float newa = 0.f;
        if (lane < CC) {
            float m = -INFINITY;
            #pragma unroll
            for (int i = 0; i < CC; i++)
                m = fmaxf(m, s_alpha[i] + s_trans[i * CC + lane]);
            float s = 0.f;
            #pragma unroll
            for (int i = 0; i < CC; i++)
                s += expf(s_alpha[i] + s_trans[i * CC + lane] - m);
            newa = m + logf(s) + lg[t * CC + lane];
        }
        __syncthreads();
        if (lane < CC) s_alpha[lane] = newa;
        __syncthreads();
    }

    float v = (lane < CC) ? s_alpha[lane] + end_s[lane] : -INFINITY;
    float m = v;
    #pragma unroll
    for (int o = 16; o; o >>= 1) m = fmaxf(m, __shfl_xor_sync(~0u, m, o));
    float e = (lane < CC) ? expf(v - m) : 0.f;
    float ss = e;
    #pragma unroll
    for (int o = 16; o; o >>= 1) ss += __shfl_xor_sync(~0u, ss, o);
    float logZ = m + logf(ss);

    float es = 0.f;
    for (int t = lane; t < len; t += 32) es += lg[t * CC + tg[t]];
    float ts = 0.f;
    for (int t = 1 + lane; t < len; t += 32) ts += s_trans[tg[t - 1] * CC + tg[t]];
    float g = es + ts;
    #pragma unroll
    for (int o = 16; o; o >>= 1) g += __shfl_xor_sync(~0u, g, o);
    if (lane == 0) {
        float gold = g + start_s[tg[0]] + end_s[tg[len - 1]];
        g_lossb[b] = logZ - gold;
    }
}

// ---------------- 7. mean reduce ----------------
__global__ void reduce_loss_kernel(float* out) {
    int lane = threadIdx.x;          // 32
    float s = g_lossb[lane] + g_lossb[lane + 32];
    #pragma unroll
    for (int o = 16; o; o >>= 1) s += __shfl_xor_sync(~0u, s, o);
    if (lane == 0) out[0] = s * (1.f / BB);
}

// ---------------- launch ----------------
extern "C" void kernel_launch(void* const* d_in, const int* in_sizes, int n_in,
                              void* d_out, int out_size) {
    const int*   words   = (const int*)  d_in[0];
    const int*   seq_len = (const int*)  d_in[1];
    const int*   target  = (const int*)  d_in[2];
    const float* table   = (const float*)d_in[3];
    const float* gamma   = (const float*)d_in[4];
    const float* beta    = (const float*)d_in[5];
    const float* w_ih_f  = (const float*)d_in[6];
    const float* w_hh_f  = (const float*)d_in[7];
    const float* b_f     = (const float*)d_in[8];
    const float* w_ih_b  = (const float*)d_in[9];
    const float* w_hh_b  = (const float*)d_in[10];
    const float* b_b     = (const float*)d_in[11];
    const float* fc_w    = (const float*)d_in[12];
    const float* fc_b    = (const float*)d_in[13];
    const float* trans   = (const float*)d_in[14];
    const float* start_s = (const float*)d_in[15];
    const float* end_s   = (const float*)d_in[16];
    float* out = (float*)d_out;

    static const int lstm_smem = LSTM_SMEM_FLOATS * (int)sizeof(float);  // 185.6 KB
    cudaFuncSetAttribute(lstm_cluster_kernel,
                         cudaFuncAttributeMaxDynamicSharedMemorySize, lstm_smem);

    embed_ln_kernel<<<M_ROWS, 256>>>(words, table, gamma, beta);
    transpose_w_kernel<<<(HH * G4 + 255) / 256, 256>>>(w_hh_f, w_hh_b);

    dim3 ggrid((G4 + 63) / 64, M_ROWS / 128, 2);
    gemm_gates_kernel<<<ggrid, 256>>>(w_ih_f, b_f, w_ih_b, b_b);

    lstm_cluster_kernel<<<16 * NRANK, 512, lstm_smem>>>(seq_len);

    logits_kernel<<<M_ROWS / 8, 256>>>(fc_w, fc_b);

    crf_kernel<<<BB, 32>>>(target, seq_len, trans, start_s, end_s);
    reduce_loss_kernel<<<1, 32>>>(out);
}